// round 12
// baseline (speedup 1.0000x reference)
#include <cuda_runtime.h>
#include <cstdint>

#define BATCH 32
#define CH    256
#define HH    56
#define WW    56
#define HW    (HH*WW)              // 3136
#define NPIX  (BATCH*HW)           // 100352
#define NELEM (BATCH*CH*HW)
#define NWORD 8
#define KTAPS 9
#define EPSBN 1e-5f

// -------------------- device scratch --------------------
__device__ __align__(16) float    g_y[NELEM];
__device__ __align__(16) uint32_t g_abits1[NPIX*NWORD];        // block1: pack(x + sh11)
__device__ __align__(16) uint32_t g_ebits [NPIX*NWORD];        // block1: e bits
__device__ __align__(16) uint32_t g_abits1b[NPIX*NWORD];       // block2: pack(y + sh21)
__device__ __align__(16) uint32_t g_ebitsb [NPIX*NWORD];       // block2: e bits
__device__ __align__(16) uint32_t g_wcol[2][KTAPS*NWORD*CH];   // [blk][(tap*8+wd)*256 + o]
__device__ int   g_popcw[2][KTAPS*CH];
__device__ float g_k1[2][CH], g_k2[2][CH], g_c0[2][CH];

// -------------------- prep --------------------
__global__ void prep_kernel(const float* __restrict__ wA, const float* __restrict__ scA,
                            const float* __restrict__ gA, const float* __restrict__ betaA,
                            const float* __restrict__ meanA, const float* __restrict__ varA,
                            const float* __restrict__ wB, const float* __restrict__ scB,
                            const float* __restrict__ gB, const float* __restrict__ betaB,
                            const float* __restrict__ meanB, const float* __restrict__ varB)
{
    const int blk = blockIdx.y;
    const float* w    = blk ? wB : wA;
    const float* sc   = blk ? scB : scA;
    const float* g    = blk ? gB : gA;
    const float* beta = blk ? betaB : betaA;
    const float* mean = blk ? meanB : meanA;
    const float* var  = blk ? varB : varA;

    const int o = blockIdx.x, tid = threadIdx.x;   // 128 threads
    __shared__ float red[128];
    __shared__ int   tapc[KTAPS];

    float s = 0.f;
    const float* wo = w + o * (CH * KTAPS);
    for (int i = tid; i < CH * KTAPS; i += 128) s += fabsf(wo[i]);
    red[tid] = s;
    __syncthreads();
    for (int st = 64; st > 0; st >>= 1) {
        if (tid < st) red[tid] += red[tid + st];
        __syncthreads();
    }
    if (tid < KTAPS) tapc[tid] = 0;
    __syncthreads();

    if (tid < KTAPS * NWORD) {
        const int tap = tid / NWORD;
        const int wd  = tid % NWORD;
        uint32_t bits = 0;
        #pragma unroll
        for (int j = 0; j < 32; j++) {
            const int c = wd * 32 + j;
            const float wv = w[(o * CH + c) * KTAPS + tap];
            bits |= (uint32_t)(wv > 0.f) << j;
        }
        g_wcol[blk][(tap * NWORD + wd) * CH + o] = bits;
        atomicAdd(&tapc[tap], __popc(bits));
    }
    __syncthreads();
    if (tid < KTAPS) g_popcw[blk][tid * CH + o] = tapc[tid];

    if (tid == 0) {
        const float alpha = red[0] / (float)(CH * KTAPS);
        const float istd  = rsqrtf(var[o] + EPSBN);
        const float k1 = alpha * istd * g[o];
        g_k1[blk][o] = k1;
        g_k2[blk][o] = sc[o] * k1;
        g_c0[blk][o] = beta[o] - mean[o] * istd * g[o];
    }
}

// -------------------- pack: fixed-global destinations (template picks block) --------------------
template<int BLK>
__global__ void pack_kernel(const float* __restrict__ in,
                            const float* __restrict__ shA, const float* __restrict__ shB)
{
    __shared__ float s1[CH], s2[CH];
    const int tid = threadIdx.x;
    s1[tid] = shA[tid]; s2[tid] = shB[tid];
    __syncthreads();

    const int pix = blockIdx.x * blockDim.x + tid;
    if (pix >= NPIX) return;
    const int b  = pix / HW;
    const int hw = pix % HW;
    const int base = b * (CH * HW) + hw;

    #pragma unroll
    for (int k = 0; k < NWORD; k++) {
        uint32_t b1 = 0, b2 = 0;
        #pragma unroll
        for (int j = 0; j < 32; j++) {
            const int c = k * 32 + j;
            const float v = in[base + c * HW];
            b1 |= (uint32_t)(v + s1[c] > 0.f) << j;
            b2 |= (uint32_t)(v + s2[c] > 0.f) << j;
        }
        if (BLK == 0) {
            g_abits1[pix * NWORD + k] = b1;
            g_ebits [pix * NWORD + k] = b1 ^ b2;
        } else {
            g_abits1b[pix * NWORD + k] = b1;
            g_ebitsb [pix * NWORD + k] = b1 ^ b2;
        }
    }
}

// -------------------- CSA popcount (combine via IMAD on fma pipe) --------------------
__device__ __forceinline__ void fa3(uint32_t a, uint32_t b, uint32_t c,
                                    uint32_t& s, uint32_t& cy) {
    s  = a ^ b ^ c;
    cy = (a & b) | (c & (a ^ b));
}

__device__ __forceinline__ int csa_popc8(uint32_t x0, uint32_t x1, uint32_t x2, uint32_t x3,
                                         uint32_t x4, uint32_t x5, uint32_t x6, uint32_t x7) {
    uint32_t s1a, c2a, s1b, c2b, s1c, c2c, s2, c4;
    fa3(x0, x1, x2, s1a, c2a);
    fa3(x3, x4, x5, s1b, c2b);
    fa3(s1a, s1b, x6, s1c, c2c);
    fa3(c2a, c2b, c2c, s2, c4);
    const int pA = __popc(s1c) + __popc(x7);
    int r;
    asm("mad.lo.s32 %0, %1, 2, %2;" : "=r"(r) : "r"(__popc(s2)), "r"(pA));
    asm("mad.lo.s32 %0, %1, 4, %2;" : "=r"(r) : "r"(__popc(c4)), "r"(r));
    return r;
}

// -------------------- conv: t3-sweep o-lane XNOR + e-sparse act2 --------------------
#define SM_W     9216
#define SM_A1    (SM_W)
#define SM_E     (SM_W + 720)
#define SM_PE    (SM_W + 1440)
#define SM_EM    (SM_W + 1485)
#define SM_TOT   (SM_W + 1512)

__global__ __launch_bounds__(256, 5)
void conv_kernel(int blk,
                 const uint32_t* __restrict__ ab1, const uint32_t* __restrict__ eb,
                 const float* __restrict__ res, float* __restrict__ out)
{
    __shared__ __align__(16) uint32_t sm[SM_TOT];

    const int tid  = threadIdx.x;
    const int warp = tid >> 5, lane = tid & 31;
    const int h     = blockIdx.x >> 1;
    const int wseg  = blockIdx.x & 1;
    const int b     = blockIdx.y;
    const int ohalf = blockIdx.z;
    const int w0    = wseg * 28;
    const int olocal = (warp & 3) * 32 + lane;
    const int o      = ohalf * 128 + olocal;
    const int pxgrp  = warp >> 2;

    // ---- stage w-half ----
    {
        const uint4* src4 = reinterpret_cast<const uint4*>(g_wcol[blk]);
        uint4* dst4 = reinterpret_cast<uint4*>(sm);
        #pragma unroll
        for (int it = 0; it < 9; it++) {
            const int idx = it * 256 + tid;
            const int tw = idx >> 5;
            const int j  = idx & 31;
            dst4[idx] = src4[tw * 64 + ohalf * 32 + j];
        }
    }
    // ---- act tiles (a1 + e) ----
    {
        const uint4* a1g = reinterpret_cast<const uint4*>(ab1);
        const uint4* eg  = reinterpret_cast<const uint4*>(eb);
        uint4* a1d = reinterpret_cast<uint4*>(sm + SM_A1);
        uint4* ed  = reinterpret_cast<uint4*>(sm + SM_E);
        for (int idx = tid; idx < 360; idx += 256) {
            const int arr  = idx / 180;
            const int cell = (idx % 180) >> 1;
            const int half = idx & 1;
            const int r = cell / 30, c = cell % 30;
            const int gh = h - 1 + r, gc = w0 - 1 + c;
            uint4 v = make_uint4(0u, 0u, 0u, 0u);
            if (gh >= 0 && gh < HH && gc >= 0 && gc < WW) {
                const int pix = (b * HH + gh) * WW + gc;
                v = (arr == 0 ? a1g : eg)[pix * 2 + half];
            }
            (arr == 0 ? a1d : ed)[cell * 2 + half] = v;
        }
    }
    __syncthreads();

    // ---- pe/emask per cell from smem e-tile ----
    {
        unsigned short* ped = reinterpret_cast<unsigned short*>(sm + SM_PE);
        uint8_t* emd = reinterpret_cast<uint8_t*>(sm + SM_EM);
        const uint4* ed = reinterpret_cast<const uint4*>(sm + SM_E);
        for (int cell = tid; cell < 90; cell += 256) {
            const uint4 e0 = ed[cell * 2];
            const uint4 e1 = ed[cell * 2 + 1];
            const int pe = __popc(e0.x) + __popc(e0.y) + __popc(e0.z) + __popc(e0.w)
                         + __popc(e1.x) + __popc(e1.y) + __popc(e1.z) + __popc(e1.w);
            int mv = (e0.x != 0u) | ((e0.y != 0u) << 1) | ((e0.z != 0u) << 2) | ((e0.w != 0u) << 3)
                   | ((e1.x != 0u) << 4) | ((e1.y != 0u) << 5) | ((e1.z != 0u) << 6) | ((e1.w != 0u) << 7);
            ped[cell] = (unsigned short)pe;
            emd[cell] = (uint8_t)mv;
        }
    }
    __syncthreads();

    const uint8_t* emd = reinterpret_cast<const uint8_t*>(sm + SM_EM);
    const uint4*   a1sm4 = reinterpret_cast<const uint4*>(sm + SM_A1);

    int acc[14];                                   // p1 low 16, delta high 16
    #pragma unroll
    for (int i = 0; i < 14; i++) acc[i] = 0;

    #pragma unroll 1
    for (int tg = 0; tg < 3; tg++) {
        const int cbase = tg * 30 + pxgrp * 14;
        #pragma unroll 1
        for (int t3 = 0; t3 < 3; t3++) {
            uint32_t wr[8];                        // only one tap's words resident
            const uint32_t wtap = (uint32_t)((tg * 3 + t3) * 8) * 128 + (uint32_t)olocal;
            #pragma unroll
            for (int i = 0; i < 8; i++) wr[i] = sm[wtap + (uint32_t)i * 128];

            #pragma unroll
            for (int pi = 0; pi < 14; pi++) {
                const int cell = cbase + pi + t3;
                const uint4 A0 = a1sm4[cell * 2];
                const uint4 A1 = a1sm4[cell * 2 + 1];
                acc[pi] += csa_popc8(
                    A0.x ^ wr[0], A0.y ^ wr[1], A0.z ^ wr[2], A0.w ^ wr[3],
                    A1.x ^ wr[4], A1.y ^ wr[5], A1.z ^ wr[6], A1.w ^ wr[7]);
                int m = emd[cell];
                while (m) {
                    const int idx = __ffs(m) - 1;
                    m &= m - 1;
                    const uint32_t e = sm[SM_E  + cell * 8 + idx];
                    const uint32_t a = sm[SM_A1 + cell * 8 + idx];
                    const uint32_t w = sm[wtap + (uint32_t)idx * 128];
                    const int p = __popc((a ^ w) & e);
                    asm("mad.lo.s32 %0, %1, 65536, %0;" : "+r"(acc[pi]) : "r"(p));
                }
            }
        }
    }

    __syncthreads();                               // wsm reads done -> reuse as stage
    float* stg = reinterpret_cast<float*>(sm);     // [128 o][29]
    const unsigned short* ped = reinterpret_cast<const unsigned short*>(sm + SM_PE);
    const int* pcw = g_popcw[blk];
    const float k1 = __ldg(&g_k1[blk][o]);
    const float k2 = __ldg(&g_k2[blk][o]);
    const float c0 = __ldg(&g_c0[blk][o]);

    #pragma unroll
    for (int pi = 0; pi < 14; pi++) {
        const int px = pxgrp * 14 + pi;
        int E = 0;
        #pragma unroll
        for (int dr = 0; dr < 3; dr++)
            #pragma unroll
            for (int dc = 0; dc < 3; dc++) E += ped[dr * 30 + px + dc];

        int corr = 0;
        {
            int mask9 = 0;
            if (h == 0)            mask9 |= 0x007;
            if (h == HH - 1)       mask9 |= 0x1C0;
            if (w0 + px == 0)      mask9 |= 0x049;
            if (w0 + px == WW - 1) mask9 |= 0x124;
            if (mask9) {
                #pragma unroll
                for (int tap = 0; tap < 9; tap++)
                    if ((mask9 >> tap) & 1)
                        corr += CH - 2 * __ldg(&pcw[tap * CH + o]);
            }
        }
        const int p1  = acc[pi] & 0xFFFF;
        const int dlt = acc[pi] >> 16;
        const int d1 = CH * KTAPS - 2 * p1 - corr;
        const int d2 = d1 - 2 * E + 4 * dlt;
        stg[olocal * 29 + px] = k1 * (float)d1 + k2 * (float)d2 + c0;
    }
    __syncthreads();

    #pragma unroll
    for (int it = 0; it < 14; it++) {
        const int id = it * 256 + tid;
        const int oL = id / 28, px = id % 28;
        const int og = ohalf * 128 + oL;
        const int gidx = (b * CH + og) * HW + h * WW + (w0 + px);
        float v = stg[oL * 29 + px] + res[gidx];
        out[gidx] = fminf(fmaxf(v, -1.0f), 1.0f);
    }
}

// -------------------- launch --------------------
extern "C" void kernel_launch(void* const* d_in, const int* in_sizes, int n_in,
                              void* d_out, int out_size)
{
    const float* x    = (const float*)d_in[0];
    const float* sh11 = (const float*)d_in[1];
    const float* sh12 = (const float*)d_in[2];
    const float* w1   = (const float*)d_in[3];
    const float* sc1  = (const float*)d_in[4];
    const float* g1   = (const float*)d_in[5];
    const float* b1   = (const float*)d_in[6];
    const float* m1   = (const float*)d_in[7];
    const float* v1   = (const float*)d_in[8];
    const float* sh21 = (const float*)d_in[9];
    const float* sh22 = (const float*)d_in[10];
    const float* w2   = (const float*)d_in[11];
    const float* sc2  = (const float*)d_in[12];
    const float* g2   = (const float*)d_in[13];
    const float* m2   = (const float*)d_in[15];
    const float* b2   = (const float*)d_in[14];
    const float* v2   = (const float*)d_in[16];
    float* outp = (float*)d_out;

    void *yp_raw, *a1a, *ea, *a1b, *ebv;
    cudaGetSymbolAddress(&yp_raw, g_y);
    cudaGetSymbolAddress(&a1a, g_abits1);
    cudaGetSymbolAddress(&ea,  g_ebits);
    cudaGetSymbolAddress(&a1b, g_abits1b);
    cudaGetSymbolAddress(&ebv, g_ebitsb);
    float* yp = (float*)yp_raw;

    dim3 pgrid(CH, 2);
    prep_kernel<<<pgrid, 128>>>(w1, sc1, g1, b1, m1, v1,
                                w2, sc2, g2, b2, m2, v2);

    dim3 cgrid(112, BATCH, 2);

    pack_kernel<0><<<(NPIX + 255) / 256, 256>>>(x, sh11, sh12);
    conv_kernel<<<cgrid, 256>>>(0, (const uint32_t*)a1a, (const uint32_t*)ea, x, yp);

    pack_kernel<1><<<(NPIX + 255) / 256, 256>>>(yp, sh21, sh22);
    conv_kernel<<<cgrid, 256>>>(1, (const uint32_t*)a1b, (const uint32_t*)ebv, yp, outp);
}

// round 13
// speedup vs baseline: 1.0727x; 1.0727x over previous
#include <cuda_runtime.h>
#include <cstdint>

#define BATCH 32
#define CH    256
#define HH    56
#define WW    56
#define HW    (HH*WW)              // 3136
#define NPIX  (BATCH*HW)           // 100352
#define NELEM (BATCH*CH*HW)
#define NWORD 8
#define KTAPS 9
#define EPSBN 1e-5f

// -------------------- device scratch --------------------
__device__ __align__(16) float    g_y[NELEM];
__device__ __align__(16) uint32_t g_abits1[NPIX*NWORD];        // pack(in + shA); reused by both sub-blocks
__device__ __align__(16) uint32_t g_ebits [NPIX*NWORD];        // e = a1^a2 bits
__device__ __align__(16) uint32_t g_wcol[2][KTAPS*NWORD*CH];   // [blk][(tap*8+wd)*256 + o]
__device__ int   g_popcw[2][KTAPS*CH];
__device__ float g_k1[2][CH], g_k2[2][CH], g_c0[2][CH];

// -------------------- prep --------------------
__global__ void prep_kernel(const float* __restrict__ wA, const float* __restrict__ scA,
                            const float* __restrict__ gA, const float* __restrict__ betaA,
                            const float* __restrict__ meanA, const float* __restrict__ varA,
                            const float* __restrict__ wB, const float* __restrict__ scB,
                            const float* __restrict__ gB, const float* __restrict__ betaB,
                            const float* __restrict__ meanB, const float* __restrict__ varB)
{
    const int blk = blockIdx.y;
    const float* w    = blk ? wB : wA;
    const float* sc   = blk ? scB : scA;
    const float* g    = blk ? gB : gA;
    const float* beta = blk ? betaB : betaA;
    const float* mean = blk ? meanB : meanA;
    const float* var  = blk ? varB : varA;

    const int o = blockIdx.x, tid = threadIdx.x;   // 128 threads
    __shared__ float red[128];
    __shared__ int   tapc[KTAPS];

    float s = 0.f;
    const float* wo = w + o * (CH * KTAPS);
    for (int i = tid; i < CH * KTAPS; i += 128) s += fabsf(wo[i]);
    red[tid] = s;
    __syncthreads();
    for (int st = 64; st > 0; st >>= 1) {
        if (tid < st) red[tid] += red[tid + st];
        __syncthreads();
    }
    if (tid < KTAPS) tapc[tid] = 0;
    __syncthreads();

    if (tid < KTAPS * NWORD) {
        const int tap = tid / NWORD;
        const int wd  = tid % NWORD;
        uint32_t bits = 0;
        #pragma unroll
        for (int j = 0; j < 32; j++) {
            const int c = wd * 32 + j;
            const float wv = w[(o * CH + c) * KTAPS + tap];
            bits |= (uint32_t)(wv > 0.f) << j;
        }
        g_wcol[blk][(tap * NWORD + wd) * CH + o] = bits;
        atomicAdd(&tapc[tap], __popc(bits));
    }
    __syncthreads();
    if (tid < KTAPS) g_popcw[blk][tid * CH + o] = tapc[tid];

    if (tid == 0) {
        const float alpha = red[0] / (float)(CH * KTAPS);
        const float istd  = rsqrtf(var[o] + EPSBN);
        const float k1 = alpha * istd * g[o];
        g_k1[blk][o] = k1;
        g_k2[blk][o] = sc[o] * k1;
        g_c0[blk][o] = beta[o] - mean[o] * istd * g[o];
    }
}

// -------------------- pack: float NCHW -> a1 + e bits (fixed global dests) --------------------
__global__ void pack_kernel(const float* __restrict__ in,
                            const float* __restrict__ shA, const float* __restrict__ shB)
{
    __shared__ float s1[CH], s2[CH];
    const int tid = threadIdx.x;
    s1[tid] = shA[tid]; s2[tid] = shB[tid];
    __syncthreads();

    const int pix = blockIdx.x * blockDim.x + tid;
    if (pix >= NPIX) return;
    const int b  = pix / HW;
    const int hw = pix % HW;
    const int base = b * (CH * HW) + hw;

    #pragma unroll
    for (int k = 0; k < NWORD; k++) {
        uint32_t b1 = 0, b2 = 0;
        #pragma unroll
        for (int j = 0; j < 32; j++) {
            const int c = k * 32 + j;
            const float v = in[base + c * HW];
            b1 |= (uint32_t)(v + s1[c] > 0.f) << j;
            b2 |= (uint32_t)(v + s2[c] > 0.f) << j;
        }
        g_abits1[pix * NWORD + k] = b1;
        g_ebits [pix * NWORD + k] = b1 ^ b2;
    }
}

// -------------------- CSA popcount --------------------
__device__ __forceinline__ void fa3(uint32_t a, uint32_t b, uint32_t c,
                                    uint32_t& s, uint32_t& cy) {
    s  = a ^ b ^ c;
    cy = (a & b) | (c & (a ^ b));
}

__device__ __forceinline__ int csa_popc8(uint32_t x0, uint32_t x1, uint32_t x2, uint32_t x3,
                                         uint32_t x4, uint32_t x5, uint32_t x6, uint32_t x7) {
    uint32_t s1a, c2a, s1b, c2b, s1c, c2c, s2, c4;
    fa3(x0, x1, x2, s1a, c2a);
    fa3(x3, x4, x5, s1b, c2b);
    fa3(s1a, s1b, x6, s1c, c2c);
    fa3(c2a, c2b, c2c, s2, c4);
    return __popc(s1c) + __popc(x7) + 2 * __popc(s2) + 4 * __popc(c4);
}

// -------------------- conv: cell-centric o-lane XNOR + e-sparse act2 (measured 360us config) --------------------
#define SM_W     9216
#define SM_A1    (SM_W)
#define SM_E     (SM_W + 720)
#define SM_PE    (SM_W + 1440)
#define SM_EM    (SM_W + 1485)
#define SM_TOT   (SM_W + 1512)

__global__ __launch_bounds__(256, 4)
void conv_kernel(int blk,
                 const uint32_t* __restrict__ ab1, const uint32_t* __restrict__ eb,
                 const float* __restrict__ res, float* __restrict__ out)
{
    __shared__ __align__(16) uint32_t sm[SM_TOT];

    const int tid  = threadIdx.x;
    const int warp = tid >> 5, lane = tid & 31;
    const int h     = blockIdx.x >> 1;
    const int wseg  = blockIdx.x & 1;
    const int b     = blockIdx.y;
    const int ohalf = blockIdx.z;
    const int w0    = wseg * 28;
    const int olocal = (warp & 3) * 32 + lane;
    const int o      = ohalf * 128 + olocal;
    const int pxgrp  = warp >> 2;

    // ---- stage w-half ----
    {
        const uint4* src4 = reinterpret_cast<const uint4*>(g_wcol[blk]);
        uint4* dst4 = reinterpret_cast<uint4*>(sm);
        #pragma unroll
        for (int it = 0; it < 9; it++) {
            const int idx = it * 256 + tid;
            const int tw = idx >> 5;
            const int j  = idx & 31;
            dst4[idx] = src4[tw * 64 + ohalf * 32 + j];
        }
    }
    // ---- act tiles (a1 + e) ----
    {
        const uint4* a1g = reinterpret_cast<const uint4*>(ab1);
        const uint4* eg  = reinterpret_cast<const uint4*>(eb);
        uint4* a1d = reinterpret_cast<uint4*>(sm + SM_A1);
        uint4* ed  = reinterpret_cast<uint4*>(sm + SM_E);
        for (int idx = tid; idx < 360; idx += 256) {
            const int arr  = idx / 180;
            const int cell = (idx % 180) >> 1;
            const int half = idx & 1;
            const int r = cell / 30, c = cell % 30;
            const int gh = h - 1 + r, gc = w0 - 1 + c;
            uint4 v = make_uint4(0u, 0u, 0u, 0u);
            if (gh >= 0 && gh < HH && gc >= 0 && gc < WW) {
                const int pix = (b * HH + gh) * WW + gc;
                v = (arr == 0 ? a1g : eg)[pix * 2 + half];
            }
            (arr == 0 ? a1d : ed)[cell * 2 + half] = v;
        }
    }
    __syncthreads();

    // ---- pe/emask per cell from smem e-tile ----
    {
        unsigned short* ped = reinterpret_cast<unsigned short*>(sm + SM_PE);
        uint8_t* emd = reinterpret_cast<uint8_t*>(sm + SM_EM);
        const uint4* ed = reinterpret_cast<const uint4*>(sm + SM_E);
        for (int cell = tid; cell < 90; cell += 256) {
            const uint4 e0 = ed[cell * 2];
            const uint4 e1 = ed[cell * 2 + 1];
            const int pe = __popc(e0.x) + __popc(e0.y) + __popc(e0.z) + __popc(e0.w)
                         + __popc(e1.x) + __popc(e1.y) + __popc(e1.z) + __popc(e1.w);
            int mv = (e0.x != 0u) | ((e0.y != 0u) << 1) | ((e0.z != 0u) << 2) | ((e0.w != 0u) << 3)
                   | ((e1.x != 0u) << 4) | ((e1.y != 0u) << 5) | ((e1.z != 0u) << 6) | ((e1.w != 0u) << 7);
            ped[cell] = (unsigned short)pe;
            emd[cell] = (uint8_t)mv;
        }
    }
    __syncthreads();

    const float k1 = __ldg(&g_k1[blk][o]);
    const float k2 = __ldg(&g_k2[blk][o]);
    const float c0 = __ldg(&g_c0[blk][o]);
    const uint8_t* emd = reinterpret_cast<const uint8_t*>(sm + SM_EM);
    const uint4*   a1sm4 = reinterpret_cast<const uint4*>(sm + SM_A1);

    int acc[14];                                   // p1 low 16, delta high 16
    #pragma unroll
    for (int i = 0; i < 14; i++) acc[i] = 0;

    #pragma unroll 1
    for (int tg = 0; tg < 3; tg++) {
        uint32_t wr[24];
        #pragma unroll
        for (int i = 0; i < 24; i++)
            wr[i] = sm[((tg * 3 + i / 8) * 8 + (i & 7)) * 128 + olocal];
        const int cbase = tg * 30 + pxgrp * 14;
        const uint32_t wbase = (uint32_t)(tg * 3) * 8 * 128 + (uint32_t)olocal;

        #pragma unroll
        for (int cc = 0; cc < 16; cc++) {
            const int cell = cbase + cc;
            const uint4 A0 = a1sm4[cell * 2];
            const uint4 A1 = a1sm4[cell * 2 + 1];
            #pragma unroll
            for (int t3 = 0; t3 < 3; t3++) {
                const int pi = cc - t3;
                if (pi >= 0 && pi < 14) {
                    acc[pi] += csa_popc8(
                        A0.x ^ wr[t3*8+0], A0.y ^ wr[t3*8+1],
                        A0.z ^ wr[t3*8+2], A0.w ^ wr[t3*8+3],
                        A1.x ^ wr[t3*8+4], A1.y ^ wr[t3*8+5],
                        A1.z ^ wr[t3*8+6], A1.w ^ wr[t3*8+7]);
                }
            }
            int m = emd[cell];
            while (m) {
                const int idx = __ffs(m) - 1;
                m &= m - 1;
                const uint32_t e = sm[SM_E  + cell * 8 + idx];
                const uint32_t a = sm[SM_A1 + cell * 8 + idx];
                #pragma unroll
                for (int t3 = 0; t3 < 3; t3++) {
                    const int pi = cc - t3;
                    if (pi >= 0 && pi < 14) {
                        const uint32_t w = sm[wbase + (uint32_t)(t3 * 8 + idx) * 128];
                        acc[pi] += __popc((a ^ w) & e) << 16;
                    }
                }
            }
        }
    }

    __syncthreads();                               // wsm reads done -> reuse as stage
    float* stg = reinterpret_cast<float*>(sm);     // [128 o][29]
    const unsigned short* ped = reinterpret_cast<const unsigned short*>(sm + SM_PE);
    const int* pcw = g_popcw[blk];

    #pragma unroll
    for (int pi = 0; pi < 14; pi++) {
        const int px = pxgrp * 14 + pi;
        int E = 0;
        #pragma unroll
        for (int dr = 0; dr < 3; dr++)
            #pragma unroll
            for (int dc = 0; dc < 3; dc++) E += ped[dr * 30 + px + dc];

        int corr = 0;
        {
            int mask9 = 0;
            if (h == 0)            mask9 |= 0x007;
            if (h == HH - 1)       mask9 |= 0x1C0;
            if (w0 + px == 0)      mask9 |= 0x049;
            if (w0 + px == WW - 1) mask9 |= 0x124;
            if (mask9) {
                #pragma unroll
                for (int tap = 0; tap < 9; tap++)
                    if ((mask9 >> tap) & 1)
                        corr += CH - 2 * __ldg(&pcw[tap * CH + o]);
            }
        }
        const int p1  = acc[pi] & 0xFFFF;
        const int dlt = acc[pi] >> 16;
        const int d1 = CH * KTAPS - 2 * p1 - corr;
        const int d2 = d1 - 2 * E + 4 * dlt;
        stg[olocal * 29 + px] = k1 * (float)d1 + k2 * (float)d2 + c0;
    }
    __syncthreads();

    #pragma unroll
    for (int it = 0; it < 14; it++) {
        const int id = it * 256 + tid;
        const int oL = id / 28, px = id % 28;
        const int og = ohalf * 128 + oL;
        const int gidx = (b * CH + og) * HW + h * WW + (w0 + px);
        float v = stg[oL * 29 + px] + res[gidx];
        out[gidx] = fminf(fmaxf(v, -1.0f), 1.0f);
    }
}

// -------------------- launch --------------------
extern "C" void kernel_launch(void* const* d_in, const int* in_sizes, int n_in,
                              void* d_out, int out_size)
{
    const float* x    = (const float*)d_in[0];
    const float* sh11 = (const float*)d_in[1];
    const float* sh12 = (const float*)d_in[2];
    const float* w1   = (const float*)d_in[3];
    const float* sc1  = (const float*)d_in[4];
    const float* g1   = (const float*)d_in[5];
    const float* b1   = (const float*)d_in[6];
    const float* m1   = (const float*)d_in[7];
    const float* v1   = (const float*)d_in[8];
    const float* sh21 = (const float*)d_in[9];
    const float* sh22 = (const float*)d_in[10];
    const float* w2   = (const float*)d_in[11];
    const float* sc2  = (const float*)d_in[12];
    const float* g2   = (const float*)d_in[13];
    const float* b2   = (const float*)d_in[14];
    const float* m2   = (const float*)d_in[15];
    const float* v2   = (const float*)d_in[16];
    float* outp = (float*)d_out;

    void *yp_raw, *a1a, *ea;
    cudaGetSymbolAddress(&yp_raw, g_y);
    cudaGetSymbolAddress(&a1a, g_abits1);
    cudaGetSymbolAddress(&ea,  g_ebits);
    float* yp = (float*)yp_raw;

    dim3 pgrid(CH, 2);
    prep_kernel<<<pgrid, 128>>>(w1, sc1, g1, b1, m1, v1,
                                w2, sc2, g2, b2, m2, v2);

    dim3 cgrid(112, BATCH, 2);

    // sub-block 1
    pack_kernel<<<(NPIX + 255) / 256, 256>>>(x, sh11, sh12);
    conv_kernel<<<cgrid, 256>>>(0, (const uint32_t*)a1a, (const uint32_t*)ea, x, yp);

    // sub-block 2 (same bit arrays reused; stream-ordered)
    pack_kernel<<<(NPIX + 255) / 256, 256>>>(yp, sh21, sh22);
    conv_kernel<<<cgrid, 256>>>(1, (const uint32_t*)a1a, (const uint32_t*)ea, yp, outp);
}

// round 14
// speedup vs baseline: 1.1229x; 1.0468x over previous
#include <cuda_runtime.h>
#include <cstdint>

#define BATCH 32
#define CH    256
#define HH    56
#define WW    56
#define HW    (HH*WW)              // 3136
#define HW4   (HW/4)               // 784
#define NPIX  (BATCH*HW)           // 100352
#define NELEM (BATCH*CH*HW)
#define NWORD 8
#define KTAPS 9
#define EPSBN 1e-5f

// -------------------- device scratch --------------------
__device__ __align__(16) float    g_y[NELEM];
__device__ __align__(16) uint32_t g_abits1[NPIX*NWORD];        // pack(in + shA); reused by both sub-blocks
__device__ __align__(16) uint32_t g_ebits [NPIX*NWORD];        // e = a1^a2 bits
__device__ __align__(16) uint32_t g_wcol[2][KTAPS*NWORD*CH];   // [blk][(tap*8+wd)*256 + o]
__device__ int   g_popcw[2][KTAPS*CH];
__device__ float g_k1[2][CH], g_k2[2][CH], g_c0[2][CH];

// -------------------- prep --------------------
__global__ void prep_kernel(const float* __restrict__ wA, const float* __restrict__ scA,
                            const float* __restrict__ gA, const float* __restrict__ betaA,
                            const float* __restrict__ meanA, const float* __restrict__ varA,
                            const float* __restrict__ wB, const float* __restrict__ scB,
                            const float* __restrict__ gB, const float* __restrict__ betaB,
                            const float* __restrict__ meanB, const float* __restrict__ varB)
{
    const int blk = blockIdx.y;
    const float* w    = blk ? wB : wA;
    const float* sc   = blk ? scB : scA;
    const float* g    = blk ? gB : gA;
    const float* beta = blk ? betaB : betaA;
    const float* mean = blk ? meanB : meanA;
    const float* var  = blk ? varB : varA;

    const int o = blockIdx.x, tid = threadIdx.x;   // 128 threads
    __shared__ float red[128];
    __shared__ int   tapc[KTAPS];

    float s = 0.f;
    const float* wo = w + o * (CH * KTAPS);
    for (int i = tid; i < CH * KTAPS; i += 128) s += fabsf(wo[i]);
    red[tid] = s;
    __syncthreads();
    for (int st = 64; st > 0; st >>= 1) {
        if (tid < st) red[tid] += red[tid + st];
        __syncthreads();
    }
    if (tid < KTAPS) tapc[tid] = 0;
    __syncthreads();

    if (tid < KTAPS * NWORD) {
        const int tap = tid / NWORD;
        const int wd  = tid % NWORD;
        uint32_t bits = 0;
        #pragma unroll
        for (int j = 0; j < 32; j++) {
            const int c = wd * 32 + j;
            const float wv = w[(o * CH + c) * KTAPS + tap];
            bits |= (uint32_t)(wv > 0.f) << j;
        }
        g_wcol[blk][(tap * NWORD + wd) * CH + o] = bits;
        atomicAdd(&tapc[tap], __popc(bits));
    }
    __syncthreads();
    if (tid < KTAPS) g_popcw[blk][tid * CH + o] = tapc[tid];

    if (tid == 0) {
        const float alpha = red[0] / (float)(CH * KTAPS);
        const float istd  = rsqrtf(var[o] + EPSBN);
        const float k1 = alpha * istd * g[o];
        g_k1[blk][o] = k1;
        g_k2[blk][o] = sc[o] * k1;
        g_c0[blk][o] = beta[o] - mean[o] * istd * g[o];
    }
}

// -------------------- pack: vectorized float4 (4 pixels/thread, 2 words/thread) --------------------
// unit = (pixgroup of 4 adjacent pixels) x (k-quarter of 2 words); NPIX units total.
__global__ void pack_kernel(const float* __restrict__ in,
                            const float* __restrict__ shA, const float* __restrict__ shB)
{
    __shared__ float s1[CH], s2[CH];
    const int tid = threadIdx.x;
    s1[tid] = shA[tid]; s2[tid] = shB[tid];
    __syncthreads();

    const int gid = blockIdx.x * 256 + tid;   // 0..NPIX-1
    const int kq  = gid & 3;                  // which pair of words
    const int pg  = gid >> 2;                 // pixel group (4 adjacent pixels, same batch)
    const int pix0 = pg * 4;
    const int b   = pix0 / HW;
    const int hw4 = (pix0 % HW) / 4;
    const float4* in4 = reinterpret_cast<const float4*>(in);
    const int base4 = b * (CH * HW4) + hw4;

    #pragma unroll
    for (int kk = 0; kk < 2; kk++) {
        const int k = kq * 2 + kk;
        uint32_t b1[4] = {0, 0, 0, 0};
        uint32_t b2[4] = {0, 0, 0, 0};
        #pragma unroll
        for (int j = 0; j < 32; j++) {
            const int c = k * 32 + j;
            const float4 v = in4[base4 + c * HW4];
            const float sa = s1[c], sb = s2[c];
            b1[0] |= (uint32_t)(v.x + sa > 0.f) << j;
            b1[1] |= (uint32_t)(v.y + sa > 0.f) << j;
            b1[2] |= (uint32_t)(v.z + sa > 0.f) << j;
            b1[3] |= (uint32_t)(v.w + sa > 0.f) << j;
            b2[0] |= (uint32_t)(v.x + sb > 0.f) << j;
            b2[1] |= (uint32_t)(v.y + sb > 0.f) << j;
            b2[2] |= (uint32_t)(v.z + sb > 0.f) << j;
            b2[3] |= (uint32_t)(v.w + sb > 0.f) << j;
        }
        #pragma unroll
        for (int p = 0; p < 4; p++) {
            g_abits1[(pix0 + p) * NWORD + k] = b1[p];
            g_ebits [(pix0 + p) * NWORD + k] = b1[p] ^ b2[p];
        }
    }
}

// -------------------- CSA popcount (combines on fma pipe via IMAD) --------------------
__device__ __forceinline__ void fa3(uint32_t a, uint32_t b, uint32_t c,
                                    uint32_t& s, uint32_t& cy) {
    s  = a ^ b ^ c;
    cy = (a & b) | (c & (a ^ b));
}

__device__ __forceinline__ int csa_popc8(uint32_t x0, uint32_t x1, uint32_t x2, uint32_t x3,
                                         uint32_t x4, uint32_t x5, uint32_t x6, uint32_t x7) {
    uint32_t s1a, c2a, s1b, c2b, s1c, c2c, s2, c4;
    fa3(x0, x1, x2, s1a, c2a);
    fa3(x3, x4, x5, s1b, c2b);
    fa3(s1a, s1b, x6, s1c, c2c);
    fa3(c2a, c2b, c2c, s2, c4);
    const int pA = __popc(s1c) + __popc(x7);
    int r;
    asm("mad.lo.s32 %0, %1, 2, %2;" : "=r"(r) : "r"(__popc(s2)), "r"(pA));
    asm("mad.lo.s32 %0, %1, 4, %2;" : "=r"(r) : "r"(__popc(c4)), "r"(r));
    return r;
}

// -------------------- conv: cell-centric o-lane XNOR + e-sparse act2 --------------------
#define SM_W     9216
#define SM_A1    (SM_W)
#define SM_E     (SM_W + 720)
#define SM_PE    (SM_W + 1440)
#define SM_EM    (SM_W + 1485)
#define SM_TOT   (SM_W + 1512)

__global__ __launch_bounds__(256, 4)
void conv_kernel(int blk,
                 const uint32_t* __restrict__ ab1, const uint32_t* __restrict__ eb,
                 const float* __restrict__ res, float* __restrict__ out)
{
    __shared__ __align__(16) uint32_t sm[SM_TOT];

    const int tid  = threadIdx.x;
    const int warp = tid >> 5, lane = tid & 31;
    const int h     = blockIdx.x >> 1;
    const int wseg  = blockIdx.x & 1;
    const int b     = blockIdx.y;
    const int ohalf = blockIdx.z;
    const int w0    = wseg * 28;
    const int olocal = (warp & 3) * 32 + lane;
    const int o      = ohalf * 128 + olocal;
    const int pxgrp  = warp >> 2;

    // ---- stage w-half ----
    {
        const uint4* src4 = reinterpret_cast<const uint4*>(g_wcol[blk]);
        uint4* dst4 = reinterpret_cast<uint4*>(sm);
        #pragma unroll
        for (int it = 0; it < 9; it++) {
            const int idx = it * 256 + tid;
            const int tw = idx >> 5;
            const int j  = idx & 31;
            dst4[idx] = src4[tw * 64 + ohalf * 32 + j];
        }
    }
    // ---- act tiles (a1 + e) ----
    {
        const uint4* a1g = reinterpret_cast<const uint4*>(ab1);
        const uint4* eg  = reinterpret_cast<const uint4*>(eb);
        uint4* a1d = reinterpret_cast<uint4*>(sm + SM_A1);
        uint4* ed  = reinterpret_cast<uint4*>(sm + SM_E);
        for (int idx = tid; idx < 360; idx += 256) {
            const int arr  = idx / 180;
            const int cell = (idx % 180) >> 1;
            const int half = idx & 1;
            const int r = cell / 30, c = cell % 30;
            const int gh = h - 1 + r, gc = w0 - 1 + c;
            uint4 v = make_uint4(0u, 0u, 0u, 0u);
            if (gh >= 0 && gh < HH && gc >= 0 && gc < WW) {
                const int pix = (b * HH + gh) * WW + gc;
                v = (arr == 0 ? a1g : eg)[pix * 2 + half];
            }
            (arr == 0 ? a1d : ed)[cell * 2 + half] = v;
        }
    }
    __syncthreads();

    // ---- pe/emask per cell from smem e-tile ----
    {
        unsigned short* ped = reinterpret_cast<unsigned short*>(sm + SM_PE);
        uint8_t* emd = reinterpret_cast<uint8_t*>(sm + SM_EM);
        const uint4* ed = reinterpret_cast<const uint4*>(sm + SM_E);
        for (int cell = tid; cell < 90; cell += 256) {
            const uint4 e0 = ed[cell * 2];
            const uint4 e1 = ed[cell * 2 + 1];
            const int pe = __popc(e0.x) + __popc(e0.y) + __popc(e0.z) + __popc(e0.w)
                         + __popc(e1.x) + __popc(e1.y) + __popc(e1.z) + __popc(e1.w);
            int mv = (e0.x != 0u) | ((e0.y != 0u) << 1) | ((e0.z != 0u) << 2) | ((e0.w != 0u) << 3)
                   | ((e1.x != 0u) << 4) | ((e1.y != 0u) << 5) | ((e1.z != 0u) << 6) | ((e1.w != 0u) << 7);
            ped[cell] = (unsigned short)pe;
            emd[cell] = (uint8_t)mv;
        }
    }
    __syncthreads();

    const float k1 = __ldg(&g_k1[blk][o]);
    const float k2 = __ldg(&g_k2[blk][o]);
    const float c0 = __ldg(&g_c0[blk][o]);
    const uint8_t* emd = reinterpret_cast<const uint8_t*>(sm + SM_EM);
    const uint4*   a1sm4 = reinterpret_cast<const uint4*>(sm + SM_A1);

    int acc[14];                                   // p1 low 16, delta high 16
    #pragma unroll
    for (int i = 0; i < 14; i++) acc[i] = 0;

    #pragma unroll 1
    for (int tg = 0; tg < 3; tg++) {
        uint32_t wr[24];
        #pragma unroll
        for (int i = 0; i < 24; i++)
            wr[i] = sm[((tg * 3 + i / 8) * 8 + (i & 7)) * 128 + olocal];
        const int cbase = tg * 30 + pxgrp * 14;
        const uint32_t wbase = (uint32_t)(tg * 3) * 8 * 128 + (uint32_t)olocal;

        #pragma unroll
        for (int cc = 0; cc < 16; cc++) {
            const int cell = cbase + cc;
            const uint4 A0 = a1sm4[cell * 2];
            const uint4 A1 = a1sm4[cell * 2 + 1];
            #pragma unroll
            for (int t3 = 0; t3 < 3; t3++) {
                const int pi = cc - t3;
                if (pi >= 0 && pi < 14) {
                    acc[pi] += csa_popc8(
                        A0.x ^ wr[t3*8+0], A0.y ^ wr[t3*8+1],
                        A0.z ^ wr[t3*8+2], A0.w ^ wr[t3*8+3],
                        A1.x ^ wr[t3*8+4], A1.y ^ wr[t3*8+5],
                        A1.z ^ wr[t3*8+6], A1.w ^ wr[t3*8+7]);
                }
            }
            int m = emd[cell];
            while (m) {
                const int idx = __ffs(m) - 1;
                m &= m - 1;
                const uint32_t e = sm[SM_E  + cell * 8 + idx];
                const uint32_t a = sm[SM_A1 + cell * 8 + idx];
                #pragma unroll
                for (int t3 = 0; t3 < 3; t3++) {
                    const int pi = cc - t3;
                    if (pi >= 0 && pi < 14) {
                        const uint32_t w = sm[wbase + (uint32_t)(t3 * 8 + idx) * 128];
                        const int p = __popc((a ^ w) & e);
                        asm("mad.lo.s32 %0, %1, 65536, %0;" : "+r"(acc[pi]) : "r"(p));
                    }
                }
            }
        }
    }

    __syncthreads();                               // wsm reads done -> reuse as stage
    float* stg = reinterpret_cast<float*>(sm);     // [128 o][29]
    const unsigned short* ped = reinterpret_cast<const unsigned short*>(sm + SM_PE);
    const int* pcw = g_popcw[blk];

    #pragma unroll
    for (int pi = 0; pi < 14; pi++) {
        const int px = pxgrp * 14 + pi;
        int E = 0;
        #pragma unroll
        for (int dr = 0; dr < 3; dr++)
            #pragma unroll
            for (int dc = 0; dc < 3; dc++) E += ped[dr * 30 + px + dc];

        int corr = 0;
        {
            int mask9 = 0;
            if (h == 0)            mask9 |= 0x007;
            if (h == HH - 1)       mask9 |= 0x1C0;
            if (w0 + px == 0)      mask9 |= 0x049;
            if (w0 + px == WW - 1) mask9 |= 0x124;
            if (mask9) {
                #pragma unroll
                for (int tap = 0; tap < 9; tap++)
                    if ((mask9 >> tap) & 1)
                        corr += CH - 2 * __ldg(&pcw[tap * CH + o]);
            }
        }
        const int p1  = acc[pi] & 0xFFFF;
        const int dlt = acc[pi] >> 16;
        const int d1 = CH * KTAPS - 2 * p1 - corr;
        const int d2 = d1 - 2 * E + 4 * dlt;
        stg[olocal * 29 + px] = k1 * (float)d1 + k2 * (float)d2 + c0;
    }
    __syncthreads();

    #pragma unroll
    for (int it = 0; it < 14; it++) {
        const int id = it * 256 + tid;
        const int oL = id / 28, px = id % 28;
        const int og = ohalf * 128 + oL;
        const int gidx = (b * CH + og) * HW + h * WW + (w0 + px);
        float v = stg[oL * 29 + px] + res[gidx];
        out[gidx] = fminf(fmaxf(v, -1.0f), 1.0f);
    }
}

// -------------------- launch --------------------
extern "C" void kernel_launch(void* const* d_in, const int* in_sizes, int n_in,
                              void* d_out, int out_size)
{
    const float* x    = (const float*)d_in[0];
    const float* sh11 = (const float*)d_in[1];
    const float* sh12 = (const float*)d_in[2];
    const float* w1   = (const float*)d_in[3];
    const float* sc1  = (const float*)d_in[4];
    const float* g1   = (const float*)d_in[5];
    const float* b1   = (const float*)d_in[6];
    const float* m1   = (const float*)d_in[7];
    const float* v1   = (const float*)d_in[8];
    const float* sh21 = (const float*)d_in[9];
    const float* sh22 = (const float*)d_in[10];
    const float* w2   = (const float*)d_in[11];
    const float* sc2  = (const float*)d_in[12];
    const float* g2   = (const float*)d_in[13];
    const float* b2   = (const float*)d_in[14];
    const float* m2   = (const float*)d_in[15];
    const float* v2   = (const float*)d_in[16];
    float* outp = (float*)d_out;

    void *yp_raw, *a1a, *ea;
    cudaGetSymbolAddress(&yp_raw, g_y);
    cudaGetSymbolAddress(&a1a, g_abits1);
    cudaGetSymbolAddress(&ea,  g_ebits);
    float* yp = (float*)yp_raw;

    dim3 pgrid(CH, 2);
    prep_kernel<<<pgrid, 128>>>(w1, sc1, g1, b1, m1, v1,
                                w2, sc2, g2, b2, m2, v2);

    dim3 cgrid(112, BATCH, 2);

    // sub-block 1
    pack_kernel<<<NPIX / 256, 256>>>(x, sh11, sh12);
    conv_kernel<<<cgrid, 256>>>(0, (const uint32_t*)a1a, (const uint32_t*)ea, x, yp);

    // sub-block 2 (same bit arrays reused; stream-ordered)
    pack_kernel<<<NPIX / 256, 256>>>(yp, sh21, sh22);
    conv_kernel<<<cgrid, 256>>>(1, (const uint32_t*)a1a, (const uint32_t*)ea, yp, outp);
}